// round 8
// baseline (speedup 1.0000x reference)
#include <cuda_runtime.h>
#include <mma.h>
using namespace nvcuda;

#define B_   2
#define S_   2048
#define D_   1024
#define NH_  16
#define HD_  64
#define M_   4096
#define SS_  4194304
#define HEADSZ_ (2048*64)

// ---------------- scratch ----------------
__device__ float g_lin3[3u * 4096u * 1024u];     // q/k/v linear outputs [p][m][n]
__device__ float g_qkv[3u * 32u * 2048u * 64u];  // head layout [p*32+bh][s][d] (tf32-rounded)
__device__ float g_scores[134217728u];           // [bh][l][n] P (tf32-rounded probs)
__device__ float g_attn[32u * 2048u * 64u];      // [bh][s][d]
__device__ float g_attnT[4096u * 1024u];         // interleaved [m][d*16+h]

__device__ __forceinline__ int swz(int n) { return n ^ ((n >> 5) & 31); }

__device__ __forceinline__ float tf32r(float x) {
    float y;
    asm("cvt.rna.tf32.f32 %0, %1;" : "=f"(y) : "f"(x));
    return y;
}

__device__ __forceinline__ void cpa16(void* dst, const void* src) {
    unsigned d = (unsigned)__cvta_generic_to_shared(dst);
    asm volatile("cp.async.ca.shared.global [%0], [%1], 16;\n" :: "r"(d), "l"(src));
}

// ============ tf32 GEMM: C[4096,1024] = A @ W + bias (cvt at smem store) ============
__global__ void __launch_bounds__(256) gemm_wmma(const float* __restrict__ A,
                                                 const float* __restrict__ W,
                                                 const float* __restrict__ bias,
                                                 float* __restrict__ C,
                                                 int asel, int csel)
{
    if (asel >= 0) A = g_attnT;
    if (csel >= 0) C = g_lin3 + (size_t)csel * 4194304u;

    __shared__ float As[128][36];
    __shared__ float Bs[32][132];
    __shared__ float stage[8][16][20];

    const int tid = threadIdx.x;
    const int warpId = tid >> 5, lane = tid & 31;
    const int wr = warpId >> 2, wc = warpId & 3;
    const int mBase = blockIdx.y * 128, nBase = blockIdx.x * 128;

    wmma::fragment<wmma::accumulator, 16, 16, 8, float> acc[4][2];
#pragma unroll
    for (int i = 0; i < 4; i++)
#pragma unroll
        for (int j = 0; j < 2; j++) wmma::fill_fragment(acc[i][j], 0.0f);

    for (int k0 = 0; k0 < 1024; k0 += 32) {
#pragma unroll
        for (int p = 0; p < 4; p++) {
            int r = p * 32 + (tid >> 3);
            int c = (tid & 7) * 4;
            float4 v = *(const float4*)(A + (size_t)(mBase + r) * 1024 + k0 + c);
            As[r][c + 0] = tf32r(v.x); As[r][c + 1] = tf32r(v.y);
            As[r][c + 2] = tf32r(v.z); As[r][c + 3] = tf32r(v.w);
        }
#pragma unroll
        for (int p = 0; p < 4; p++) {
            int r = p * 8 + (tid >> 5);
            int c = (tid & 31) * 4;
            float4 v = *(const float4*)(W + (size_t)(k0 + r) * 1024 + nBase + c);
            Bs[r][c + 0] = tf32r(v.x); Bs[r][c + 1] = tf32r(v.y);
            Bs[r][c + 2] = tf32r(v.z); Bs[r][c + 3] = tf32r(v.w);
        }
        __syncthreads();

#pragma unroll
        for (int ks = 0; ks < 4; ks++) {
            wmma::fragment<wmma::matrix_a, 16, 16, 8, wmma::precision::tf32, wmma::row_major> af[4];
            wmma::fragment<wmma::matrix_b, 16, 16, 8, wmma::precision::tf32, wmma::row_major> bf[2];
#pragma unroll
            for (int i = 0; i < 4; i++)
                wmma::load_matrix_sync(af[i], &As[wr * 64 + i * 16][ks * 8], 36);
#pragma unroll
            for (int j = 0; j < 2; j++)
                wmma::load_matrix_sync(bf[j], &Bs[ks * 8][wc * 32 + j * 16], 132);
#pragma unroll
            for (int i = 0; i < 4; i++)
#pragma unroll
                for (int j = 0; j < 2; j++)
                    wmma::mma_sync(acc[i][j], af[i], bf[j], acc[i][j]);
        }
        __syncthreads();
    }

#pragma unroll
    for (int i = 0; i < 4; i++) {
#pragma unroll
        for (int j = 0; j < 2; j++) {
            wmma::store_matrix_sync(&stage[warpId][0][0], acc[i][j], 20, wmma::mem_row_major);
            __syncwarp();
            int r = lane >> 1, c0 = (lane & 1) * 8;
            int row = mBase + wr * 64 + i * 16 + r;
            int col = nBase + wc * 32 + j * 16 + c0;
            const float* sp = &stage[warpId][r][c0];
            float4 v0, v1;
            v0.x = sp[0] + bias[col + 0]; v0.y = sp[1] + bias[col + 1];
            v0.z = sp[2] + bias[col + 2]; v0.w = sp[3] + bias[col + 3];
            v1.x = sp[4] + bias[col + 4]; v1.y = sp[5] + bias[col + 5];
            v1.z = sp[6] + bias[col + 6]; v1.w = sp[7] + bias[col + 7];
            *(float4*)(C + (size_t)row * 1024 + col) = v0;
            *(float4*)(C + (size_t)row * 1024 + col + 4) = v1;
            __syncwarp();
        }
    }
}

// ---------------- interleaved -> head layout, tf32-rounded ----------------
__global__ void __launch_bounds__(256) trans_qkv_kernel()
{
    __shared__ float buf[8][1024];
    const int w = threadIdx.x >> 5, lane = threadIdx.x & 31;
    const int r = blockIdx.x * 8 + w;
    const int p = r >> 12;
    const int bs = r & 4095;
    const int b = bs >> 11, s = bs & 2047;

    const float* src = g_lin3 + (size_t)r * 1024;
#pragma unroll
    for (int i = 0; i < 8; i++) {
        int n0 = i * 128 + lane * 4;
        float4 v = *(const float4*)(src + n0);
        buf[w][swz(n0 + 0)] = v.x;
        buf[w][swz(n0 + 1)] = v.y;
        buf[w][swz(n0 + 2)] = v.z;
        buf[w][swz(n0 + 3)] = v.w;
    }
    __syncwarp();
    float* dstBase = g_qkv + ((size_t)p * 32 + (size_t)b * 16) * HEADSZ_ + (size_t)s * 64;
#pragma unroll
    for (int h = 0; h < 16; h++) {
        float* dst = dstBase + (size_t)h * HEADSZ_;
#pragma unroll
        for (int half = 0; half < 2; half++) {
            int d = half * 32 + lane;
            dst[d] = tf32r(buf[w][swz(d * 16 + h)]);
        }
    }
}

// ============ Fused QK + head-softmax + probs write + P write ============
// CTA tile: l=32, n=64, all 16 heads. 8 warps (2l x 4n), warp tile 16x16.
// Dynamic smem: Qs[2][32][68] then Ks[2][64][68].
#define QS_(b_, r_, c_) sm[(b_)*2176 + (r_)*68 + (c_)]
#define KS_(b_, r_, c_) sm[4352 + (b_)*4352 + (r_)*68 + (c_)]

__global__ void __launch_bounds__(256) qk_softmax(float* __restrict__ probs_out)
{
    extern __shared__ float sm[];

    const int tid = threadIdx.x;
    const int warpId = tid >> 5;
    const int wl = warpId >> 2, wn = warpId & 3;
    const int n0 = blockIdx.x * 64;
    const int l0 = blockIdx.y * 32;
    const int b  = blockIdx.z;

    // ---- discover accumulator fragment (row,col) mapping at runtime ----
    float idx_rc[8];
    {
        // A[16][8]: col0 = r, col1 = 1. B[8][16]: row0 = 16, row1 = c. C[r][c] = 16r + c.
        for (int i = tid; i < 128; i += 256) {
            int r = i >> 3, k = i & 7;
            sm[i] = (k == 0) ? (float)r : (k == 1 ? 1.0f : 0.0f);
        }
        for (int i = tid; i < 128; i += 256) {
            int k = i >> 4, c = i & 15;
            sm[128 + i] = (k == 0) ? 16.0f : (k == 1 ? (float)c : 0.0f);
        }
        __syncthreads();
        wmma::fragment<wmma::matrix_a, 16, 16, 8, wmma::precision::tf32, wmma::row_major> af;
        wmma::fragment<wmma::matrix_b, 16, 16, 8, wmma::precision::tf32, wmma::row_major> bf;
        wmma::fragment<wmma::accumulator, 16, 16, 8, float> ac;
        wmma::fill_fragment(ac, 0.0f);
        wmma::load_matrix_sync(af, sm, 8);
        wmma::load_matrix_sync(bf, sm + 128, 16);
        wmma::mma_sync(ac, af, bf, ac);
#pragma unroll
        for (int t = 0; t < 8; t++) idx_rc[t] = ac.x[t];
        __syncthreads();
    }

    wmma::fragment<wmma::accumulator, 16, 16, 8, float> acc[16];
#pragma unroll
    for (int h = 0; h < 16; h++) wmma::fill_fragment(acc[h], 0.0f);

    // ---- cp.async tile loader (Q: 32x64, K: 64x64 per head) ----
    auto load_head = [&](int h, int bb) {
        const float* Qp = g_qkv + (size_t)(b * 16 + h) * HEADSZ_;
        const float* Kp = g_qkv + (size_t)(32 + b * 16 + h) * HEADSZ_;
#pragma unroll
        for (int i = 0; i < 2; i++) {
            int f = tid + i * 256;
            int r = f >> 4, c = (f & 15) * 4;
            cpa16(&QS_(bb, r, c), Qp + (size_t)(l0 + r) * 64 + c);
        }
#pragma unroll
        for (int i = 0; i < 4; i++) {
            int f = tid + i * 256;
            int r = f >> 4, c = (f & 15) * 4;
            cpa16(&KS_(bb, r, c), Kp + (size_t)(n0 + r) * 64 + c);
        }
        asm volatile("cp.async.commit_group;\n");
    };

    load_head(0, 0);

    for (int h = 0; h < 16; h++) {
        const int bb = h & 1;
        if (h < 15) {
            load_head(h + 1, bb ^ 1);
            asm volatile("cp.async.wait_group 1;\n");
        } else {
            asm volatile("cp.async.wait_group 0;\n");
        }
        __syncthreads();

        wmma::fragment<wmma::matrix_a, 16, 16, 8, wmma::precision::tf32, wmma::row_major> af;
        wmma::fragment<wmma::matrix_b, 16, 16, 8, wmma::precision::tf32, wmma::col_major> bf;
#pragma unroll
        for (int ks = 0; ks < 8; ks++) {
            wmma::load_matrix_sync(af, &QS_(bb, wl * 16, ks * 8), 68);
            wmma::load_matrix_sync(bf, &KS_(bb, wn * 16, ks * 8), 68);
            wmma::mma_sync(acc[h], af, bf, acc[h]);
        }
        __syncthreads();
    }

    // ---- softmax over the 16 heads, per accumulator element ----
#pragma unroll
    for (int t = 0; t < 8; t++) {
        float mx = -1e30f;
#pragma unroll
        for (int h = 0; h < 16; h++) mx = fmaxf(mx, acc[h].x[t]);
        mx *= 0.125f;
        float s = 0.f;
#pragma unroll
        for (int h = 0; h < 16; h++) {
            float e = __expf(acc[h].x[t] * 0.125f - mx);
            acc[h].x[t] = e;
            s += e;
        }
        float inv = 1.0f / s;
#pragma unroll
        for (int h = 0; h < 16; h++) acc[h].x[t] *= inv;
    }

    // ---- write probs [b][l][n][h] (exact fp32), 64B per (l,n) ----
    if (probs_out) {
#pragma unroll
        for (int t = 0; t < 8; t++) {
            int rc = __float2int_rn(idx_rc[t]);
            int r = rc >> 4, c = rc & 15;
            size_t l = (size_t)(l0 + wl * 16 + r);
            size_t n = (size_t)(n0 + wn * 16 + c);
            float4* dst = (float4*)(probs_out + (((size_t)b * 2048 + l) * 2048 + n) * 16);
            dst[0] = make_float4(acc[0].x[t],  acc[1].x[t],  acc[2].x[t],  acc[3].x[t]);
            dst[1] = make_float4(acc[4].x[t],  acc[5].x[t],  acc[6].x[t],  acc[7].x[t]);
            dst[2] = make_float4(acc[8].x[t],  acc[9].x[t],  acc[10].x[t], acc[11].x[t]);
            dst[3] = make_float4(acc[12].x[t], acc[13].x[t], acc[14].x[t], acc[15].x[t]);
        }
    }

    // ---- write P planes [bh][l][n] tf32-rounded (AV operand) ----
#pragma unroll
    for (int h = 0; h < 16; h++) {
#pragma unroll
        for (int t = 0; t < 8; t++) acc[h].x[t] = tf32r(acc[h].x[t]);
        float* Pp = g_scores + (size_t)(b * 16 + h) * SS_ +
                    (size_t)(l0 + wl * 16) * 2048 + (n0 + wn * 16);
        wmma::store_matrix_sync(Pp, acc[h], 2048, wmma::mem_row_major);
    }
}

// ============ tf32 AV: attn = P @ V (operands pre-rounded) ============
__global__ void __launch_bounds__(256) av_wmma()
{
    __shared__ float Ps[128][36];
    __shared__ float Vs[32][68];
    const int tid = threadIdx.x;
    const int warpId = tid >> 5;
    const int wr = warpId >> 1, wc = warpId & 1;
    const int bh = blockIdx.y;
    const int mBase = blockIdx.x * 128;
    const float* P = g_scores + (size_t)bh * SS_;
    const float* V = g_qkv + (size_t)(64 + bh) * HEADSZ_;

    wmma::fragment<wmma::accumulator, 16, 16, 8, float> acc[2][2];
#pragma unroll
    for (int i = 0; i < 2; i++)
#pragma unroll
        for (int j = 0; j < 2; j++) wmma::fill_fragment(acc[i][j], 0.0f);

    for (int k0 = 0; k0 < 2048; k0 += 32) {
#pragma unroll
        for (int p = 0; p < 4; p++) {
            int r = p * 32 + (tid >> 3);
            int c = (tid & 7) * 4;
            *(float4*)&Ps[r][c] = *(const float4*)(P + (size_t)(mBase + r) * 2048 + k0 + c);
        }
#pragma unroll
        for (int p = 0; p < 2; p++) {
            int r = p * 16 + (tid >> 4);
            int c = (tid & 15) * 4;
            *(float4*)&Vs[r][c] = *(const float4*)(V + (size_t)(k0 + r) * 64 + c);
        }
        __syncthreads();

#pragma unroll
        for (int ks = 0; ks < 4; ks++) {
            wmma::fragment<wmma::matrix_a, 16, 16, 8, wmma::precision::tf32, wmma::row_major> af[2];
            wmma::fragment<wmma::matrix_b, 16, 16, 8, wmma::precision::tf32, wmma::row_major> bf[2];
#pragma unroll
            for (int i = 0; i < 2; i++)
                wmma::load_matrix_sync(af[i], &Ps[wr * 32 + i * 16][ks * 8], 36);
#pragma unroll
            for (int j = 0; j < 2; j++)
                wmma::load_matrix_sync(bf[j], &Vs[ks * 8][wc * 32 + j * 16], 68);
#pragma unroll
            for (int i = 0; i < 2; i++)
#pragma unroll
                for (int j = 0; j < 2; j++)
                    wmma::mma_sync(acc[i][j], af[i], bf[j], acc[i][j]);
        }
        __syncthreads();
    }

    float* C = g_attn + (size_t)bh * HEADSZ_;
#pragma unroll
    for (int i = 0; i < 2; i++)
#pragma unroll
        for (int j = 0; j < 2; j++)
            wmma::store_matrix_sync(C + (size_t)(mBase + wr * 32 + i * 16) * 64 +
                                    (wc * 32 + j * 16),
                                    acc[i][j], 64, wmma::mem_row_major);
}

// ---------------- head layout -> interleaved ----------------
__global__ void __launch_bounds__(256) trans_attn_kernel()
{
    __shared__ float buf[8][1024];
    const int w = threadIdx.x >> 5, lane = threadIdx.x & 31;
    const int r = blockIdx.x * 8 + w;
    const int b = r >> 11, s = r & 2047;

    const float* srcBase = g_attn + (size_t)b * 16u * HEADSZ_ + (size_t)s * 64;
#pragma unroll
    for (int h = 0; h < 16; h++) {
        const float* src = srcBase + (size_t)h * HEADSZ_;
#pragma unroll
        for (int half = 0; half < 2; half++) {
            int d = half * 32 + lane;
            buf[w][swz(d * 16 + h)] = src[d];
        }
    }
    __syncwarp();
    float* dst = g_attnT + (size_t)r * 1024;
#pragma unroll
    for (int i = 0; i < 8; i++) {
        int n0 = i * 128 + lane * 4;
        float4 v;
        v.x = buf[w][swz(n0 + 0)];
        v.y = buf[w][swz(n0 + 1)];
        v.z = buf[w][swz(n0 + 2)];
        v.w = buf[w][swz(n0 + 3)];
        *(float4*)(dst + n0) = v;
    }
}

// ---------------- launch ----------------
extern "C" void kernel_launch(void* const* d_in, const int* in_sizes, int n_in,
                              void* d_out, int out_size)
{
    const float* q  = (const float*)d_in[0];
    const float* k  = (const float*)d_in[1];
    const float* v  = (const float*)d_in[2];
    const float* Wq = (const float*)d_in[3];
    const float* bq = (const float*)d_in[4];
    const float* Wk = (const float*)d_in[5];
    const float* bk = (const float*)d_in[6];
    const float* Wv = (const float*)d_in[7];
    const float* bv = (const float*)d_in[8];
    const float* Wo = (const float*)d_in[9];
    const float* bo = (const float*)d_in[10];

    float* out = (float*)d_out;
    float* probs = (out_size >= 138412032) ? out + 4194304 : nullptr;

    // (2*32*68 + 2*64*68) floats = 52224 bytes dynamic smem for qk_softmax
    static int smem_set = 0;
    if (!smem_set) {
        cudaFuncSetAttribute(qk_softmax, cudaFuncAttributeMaxDynamicSharedMemorySize, 52224);
        smem_set = 1;
    }

    dim3 gemmGrid(8, 32, 1);
    gemm_wmma<<<gemmGrid, 256>>>(q, Wq, bq, nullptr, -1, 0);
    gemm_wmma<<<gemmGrid, 256>>>(k, Wk, bk, nullptr, -1, 1);
    gemm_wmma<<<gemmGrid, 256>>>(v, Wv, bv, nullptr, -1, 2);

    trans_qkv_kernel<<<1536, 256>>>();

    // fused QK + softmax(head axis) + probs + P
    qk_softmax<<<dim3(32, 64, 2), 256, 52224>>>(probs);

    av_wmma<<<dim3(16, 32), 256>>>();

    trans_attn_kernel<<<512, 256>>>();

    gemm_wmma<<<gemmGrid, 256>>>(nullptr, Wo, bo, out, 0, -1);
}

// round 10
// speedup vs baseline: 1.2551x; 1.2551x over previous
#include <cuda_runtime.h>
#include <mma.h>
using namespace nvcuda;

#define B_   2
#define S_   2048
#define D_   1024
#define NH_  16
#define HD_  64
#define M_   4096
#define SS_  4194304
#define HEADSZ_ (2048*64)

// ---------------- scratch ----------------
__device__ float g_lin3[3u * 4096u * 1024u];     // q/k/v linear outputs [p][m][n]
__device__ float g_qkv[3u * 32u * 2048u * 64u];  // head layout [p*32+bh][s][d] (tf32-rounded)
__device__ float g_scores[134217728u];           // [bh][l][n] raw scaled scores
__device__ float g_attn[32u * 2048u * 64u];      // [bh][s][d]
__device__ float g_attnT[4096u * 1024u];         // interleaved [m][d*16+h]

__device__ __forceinline__ int swz(int n) { return n ^ ((n >> 5) & 31); }

__device__ __forceinline__ float tf32r(float x) {
    float y;
    asm("cvt.rna.tf32.f32 %0, %1;" : "=f"(y) : "f"(x));
    return y;
}

__device__ __forceinline__ void cpa16(void* dst, const void* src) {
    unsigned d = (unsigned)__cvta_generic_to_shared(dst);
    asm volatile("cp.async.ca.shared.global [%0], [%1], 16;\n" :: "r"(d), "l"(src));
}

// ============ tf32 GEMM: C[4096,1024] = A @ W + bias (cvt at smem store) ============
__global__ void __launch_bounds__(256) gemm_wmma(const float* __restrict__ A,
                                                 const float* __restrict__ W,
                                                 const float* __restrict__ bias,
                                                 float* __restrict__ C,
                                                 int asel, int csel)
{
    if (asel >= 0) A = g_attnT;
    if (csel >= 0) C = g_lin3 + (size_t)csel * 4194304u;

    __shared__ float As[128][36];
    __shared__ float Bs[32][132];
    __shared__ float stage[8][16][20];

    const int tid = threadIdx.x;
    const int warpId = tid >> 5, lane = tid & 31;
    const int wr = warpId >> 2, wc = warpId & 3;
    const int mBase = blockIdx.y * 128, nBase = blockIdx.x * 128;

    wmma::fragment<wmma::accumulator, 16, 16, 8, float> acc[4][2];
#pragma unroll
    for (int i = 0; i < 4; i++)
#pragma unroll
        for (int j = 0; j < 2; j++) wmma::fill_fragment(acc[i][j], 0.0f);

    for (int k0 = 0; k0 < 1024; k0 += 32) {
#pragma unroll
        for (int p = 0; p < 4; p++) {
            int r = p * 32 + (tid >> 3);
            int c = (tid & 7) * 4;
            float4 v = *(const float4*)(A + (size_t)(mBase + r) * 1024 + k0 + c);
            As[r][c + 0] = tf32r(v.x); As[r][c + 1] = tf32r(v.y);
            As[r][c + 2] = tf32r(v.z); As[r][c + 3] = tf32r(v.w);
        }
#pragma unroll
        for (int p = 0; p < 4; p++) {
            int r = p * 8 + (tid >> 5);
            int c = (tid & 31) * 4;
            float4 v = *(const float4*)(W + (size_t)(k0 + r) * 1024 + nBase + c);
            Bs[r][c + 0] = tf32r(v.x); Bs[r][c + 1] = tf32r(v.y);
            Bs[r][c + 2] = tf32r(v.z); Bs[r][c + 3] = tf32r(v.w);
        }
        __syncthreads();

#pragma unroll
        for (int ks = 0; ks < 4; ks++) {
            wmma::fragment<wmma::matrix_a, 16, 16, 8, wmma::precision::tf32, wmma::row_major> af[4];
            wmma::fragment<wmma::matrix_b, 16, 16, 8, wmma::precision::tf32, wmma::row_major> bf[2];
#pragma unroll
            for (int i = 0; i < 4; i++)
                wmma::load_matrix_sync(af[i], &As[wr * 64 + i * 16][ks * 8], 36);
#pragma unroll
            for (int j = 0; j < 2; j++)
                wmma::load_matrix_sync(bf[j], &Bs[ks * 8][wc * 32 + j * 16], 132);
#pragma unroll
            for (int i = 0; i < 4; i++)
#pragma unroll
                for (int j = 0; j < 2; j++)
                    wmma::mma_sync(acc[i][j], af[i], bf[j], acc[i][j]);
        }
        __syncthreads();
    }

#pragma unroll
    for (int i = 0; i < 4; i++) {
#pragma unroll
        for (int j = 0; j < 2; j++) {
            wmma::store_matrix_sync(&stage[warpId][0][0], acc[i][j], 20, wmma::mem_row_major);
            __syncwarp();
            int r = lane >> 1, c0 = (lane & 1) * 8;
            int row = mBase + wr * 64 + i * 16 + r;
            int col = nBase + wc * 32 + j * 16 + c0;
            const float* sp = &stage[warpId][r][c0];
            float4 v0, v1;
            v0.x = sp[0] + bias[col + 0]; v0.y = sp[1] + bias[col + 1];
            v0.z = sp[2] + bias[col + 2]; v0.w = sp[3] + bias[col + 3];
            v1.x = sp[4] + bias[col + 4]; v1.y = sp[5] + bias[col + 5];
            v1.z = sp[6] + bias[col + 6]; v1.w = sp[7] + bias[col + 7];
            *(float4*)(C + (size_t)row * 1024 + col) = v0;
            *(float4*)(C + (size_t)row * 1024 + col + 4) = v1;
            __syncwarp();
        }
    }
}

// ---------------- interleaved -> head layout, tf32-rounded ----------------
__global__ void __launch_bounds__(256) trans_qkv_kernel()
{
    __shared__ float buf[8][1024];
    const int w = threadIdx.x >> 5, lane = threadIdx.x & 31;
    const int r = blockIdx.x * 8 + w;
    const int p = r >> 12;
    const int bs = r & 4095;
    const int b = bs >> 11, s = bs & 2047;

    const float* src = g_lin3 + (size_t)r * 1024;
#pragma unroll
    for (int i = 0; i < 8; i++) {
        int n0 = i * 128 + lane * 4;
        float4 v = *(const float4*)(src + n0);
        buf[w][swz(n0 + 0)] = v.x;
        buf[w][swz(n0 + 1)] = v.y;
        buf[w][swz(n0 + 2)] = v.z;
        buf[w][swz(n0 + 3)] = v.w;
    }
    __syncwarp();
    float* dstBase = g_qkv + ((size_t)p * 32 + (size_t)b * 16) * HEADSZ_ + (size_t)s * 64;
#pragma unroll
    for (int h = 0; h < 16; h++) {
        float* dst = dstBase + (size_t)h * HEADSZ_;
#pragma unroll
        for (int half = 0; half < 2; half++) {
            int d = half * 32 + lane;
            dst[d] = tf32r(buf[w][swz(d * 16 + h)]);
        }
    }
}

// ============ tf32 QK: scores[bh][l][n] = (Q_h @ K_h^T) / 8 (inputs pre-rounded) ============
__global__ void __launch_bounds__(256) qk_wmma()
{
    __shared__ float Qs[128][36];
    __shared__ float Ks[128][36];
    const int tid = threadIdx.x;
    const int warpId = tid >> 5;
    const int wr = warpId >> 2, wc = warpId & 3;
    const int bh = blockIdx.z;
    const int mBase = blockIdx.y * 128, nBase = blockIdx.x * 128;
    const float* Q = g_qkv + (size_t)bh * HEADSZ_;
    const float* K = g_qkv + (size_t)(32 + bh) * HEADSZ_;

    wmma::fragment<wmma::accumulator, 16, 16, 8, float> acc[4][2];
#pragma unroll
    for (int i = 0; i < 4; i++)
#pragma unroll
        for (int j = 0; j < 2; j++) wmma::fill_fragment(acc[i][j], 0.0f);

    for (int k0 = 0; k0 < 64; k0 += 32) {
#pragma unroll
        for (int p = 0; p < 4; p++) {
            int r = p * 32 + (tid >> 3);
            int c = (tid & 7) * 4;
            *(float4*)&Qs[r][c] = *(const float4*)(Q + (size_t)(mBase + r) * 64 + k0 + c);
            *(float4*)&Ks[r][c] = *(const float4*)(K + (size_t)(nBase + r) * 64 + k0 + c);
        }
        __syncthreads();

#pragma unroll
        for (int ks = 0; ks < 4; ks++) {
            wmma::fragment<wmma::matrix_a, 16, 16, 8, wmma::precision::tf32, wmma::row_major> af[4];
            wmma::fragment<wmma::matrix_b, 16, 16, 8, wmma::precision::tf32, wmma::col_major> bf[2];
#pragma unroll
            for (int i = 0; i < 4; i++)
                wmma::load_matrix_sync(af[i], &Qs[wr * 64 + i * 16][ks * 8], 36);
#pragma unroll
            for (int j = 0; j < 2; j++)
                wmma::load_matrix_sync(bf[j], &Ks[wc * 32 + j * 16][ks * 8], 36);
#pragma unroll
            for (int i = 0; i < 4; i++)
#pragma unroll
                for (int j = 0; j < 2; j++)
                    wmma::mma_sync(acc[i][j], af[i], bf[j], acc[i][j]);
        }
        __syncthreads();
    }

    float* Cp = g_scores + (size_t)bh * SS_;
#pragma unroll
    for (int i = 0; i < 4; i++)
#pragma unroll
        for (int j = 0; j < 2; j++) {
#pragma unroll
            for (int t = 0; t < acc[i][j].num_elements; t++) acc[i][j].x[t] *= 0.125f;
            wmma::store_matrix_sync(Cp + (size_t)(mBase + wr * 64 + i * 16) * 2048 +
                                    (nBase + wc * 32 + j * 16),
                                    acc[i][j], 2048, wmma::mem_row_major);
        }
}

// ============ Fused head-softmax + probs write + AV ============
// Grid (64 l-tiles, 2 b), 512 threads (16 warps = 16 heads).
// smem: double buffer, each buffer holds 16 head planes [h][32 l][36] (plane stride 1152 words).
#define PLANE_ 1152
#define BUFW_  18432            // 16 * 1152 words per buffer
#define PAV_SMEM_ (2 * BUFW_ * 4)  // 147456 bytes

__global__ void __launch_bounds__(512) pav_kernel(float* __restrict__ probs_out)
{
    extern __shared__ float sm[];
    const int tid = threadIdx.x;
    const int h = tid >> 5;          // warp = head for the mma phase
    const int l0 = blockIdx.x * 32;
    const int b  = blockIdx.y;

    wmma::fragment<wmma::accumulator, 16, 16, 8, float> accO[2][4];
#pragma unroll
    for (int i = 0; i < 2; i++)
#pragma unroll
        for (int j = 0; j < 4; j++) wmma::fill_fragment(accO[i][j], 0.0f);

    // stage all 16 head score planes for one 32-wide n chunk
    auto load_chunk = [&](int chunk, int bbuf) {
#pragma unroll
        for (int i = 0; i < 8; i++) {
            int flat = i * 512 + tid;          // 0..4095
            int hh  = flat >> 8;               // head
            int row = (flat >> 3) & 31;        // l within tile
            int seg = flat & 7;                // 16B segment within 128B row
            const float* src = g_scores + (size_t)(b * 16 + hh) * SS_ +
                               (size_t)(l0 + row) * 2048 + chunk * 32 + seg * 4;
            cpa16(&sm[bbuf * BUFW_ + hh * PLANE_ + row * 36 + seg * 4], src);
        }
        asm volatile("cp.async.commit_group;\n");
    };

    load_chunk(0, 0);

    for (int c = 0; c < 64; c++) {
        const int bbuf = c & 1;
        if (c < 63) {
            load_chunk(c + 1, bbuf ^ 1);
            asm volatile("cp.async.wait_group 1;\n");
        } else {
            asm volatile("cp.async.wait_group 0;\n");
        }
        __syncthreads();

        float* buf = sm + bbuf * BUFW_;

        // ---- softmax over heads: 2 (l,n) positions per thread ----
#pragma unroll
        for (int p = 0; p < 2; p++) {
            int pos = p * 512 + tid;           // 0..1023
            int l = pos >> 5, n = pos & 31;
            float* sp = buf + l * 36 + n;
            float v[16];
            float mx = -1e30f;
#pragma unroll
            for (int hh = 0; hh < 16; hh++) {
                v[hh] = sp[hh * PLANE_];
                mx = fmaxf(mx, v[hh]);
            }
            float s = 0.f;
#pragma unroll
            for (int hh = 0; hh < 16; hh++) {
                v[hh] = __expf(v[hh] - mx);
                s += v[hh];
            }
            float inv = 1.0f / s;
#pragma unroll
            for (int hh = 0; hh < 16; hh++) v[hh] *= inv;

            if (probs_out) {
                size_t gl = (size_t)(b * 2048 + l0 + l);
                size_t gn = (size_t)(c * 32 + n);
                float4* dst = (float4*)(probs_out + (gl * 2048 + gn) * 16);
                dst[0] = make_float4(v[0],  v[1],  v[2],  v[3]);
                dst[1] = make_float4(v[4],  v[5],  v[6],  v[7]);
                dst[2] = make_float4(v[8],  v[9],  v[10], v[11]);
                dst[3] = make_float4(v[12], v[13], v[14], v[15]);
            }
#pragma unroll
            for (int hh = 0; hh < 16; hh++) sp[hh * PLANE_] = tf32r(v[hh]);
        }
        __syncthreads();

        // ---- mma: warp h computes attn[l-tile][64] += P_h[32x32] @ V_h[32x64] ----
        {
            const float* Pp = buf + h * PLANE_;
            const float* Vp = g_qkv + (size_t)(64 + b * 16 + h) * HEADSZ_ + (size_t)(c * 32) * 64;
#pragma unroll
            for (int ks = 0; ks < 4; ks++) {
                wmma::fragment<wmma::matrix_a, 16, 16, 8, wmma::precision::tf32, wmma::row_major> af[2];
                wmma::load_matrix_sync(af[0], Pp + ks * 8, 36);
                wmma::load_matrix_sync(af[1], Pp + 16 * 36 + ks * 8, 36);
#pragma unroll
                for (int j = 0; j < 4; j++) {
                    wmma::fragment<wmma::matrix_b, 16, 16, 8, wmma::precision::tf32, wmma::row_major> bfv;
                    wmma::load_matrix_sync(bfv, Vp + (size_t)ks * 8 * 64 + j * 16, 64);
                    wmma::mma_sync(accO[0][j], af[0], bfv, accO[0][j]);
                    wmma::mma_sync(accO[1][j], af[1], bfv, accO[1][j]);
                }
            }
        }
        __syncthreads();   // protect buf from overwrite by the cp.async issued 2 chunks later
    }

    // ---- epilogue: store attn for this head ----
    float* C = g_attn + (size_t)(b * 16 + h) * HEADSZ_;
#pragma unroll
    for (int i = 0; i < 2; i++)
#pragma unroll
        for (int j = 0; j < 4; j++)
            wmma::store_matrix_sync(C + (size_t)(l0 + i * 16) * 64 + j * 16,
                                    accO[i][j], 64, wmma::mem_row_major);
}

// ---------------- head layout -> interleaved ----------------
__global__ void __launch_bounds__(256) trans_attn_kernel()
{
    __shared__ float buf[8][1024];
    const int w = threadIdx.x >> 5, lane = threadIdx.x & 31;
    const int r = blockIdx.x * 8 + w;
    const int b = r >> 11, s = r & 2047;

    const float* srcBase = g_attn + (size_t)b * 16u * HEADSZ_ + (size_t)s * 64;
#pragma unroll
    for (int h = 0; h < 16; h++) {
        const float* src = srcBase + (size_t)h * HEADSZ_;
#pragma unroll
        for (int half = 0; half < 2; half++) {
            int d = half * 32 + lane;
            buf[w][swz(d * 16 + h)] = src[d];
        }
    }
    __syncwarp();
    float* dst = g_attnT + (size_t)r * 1024;
#pragma unroll
    for (int i = 0; i < 8; i++) {
        int n0 = i * 128 + lane * 4;
        float4 v;
        v.x = buf[w][swz(n0 + 0)];
        v.y = buf[w][swz(n0 + 1)];
        v.z = buf[w][swz(n0 + 2)];
        v.w = buf[w][swz(n0 + 3)];
        *(float4*)(dst + n0) = v;
    }
}

// ---------------- launch ----------------
extern "C" void kernel_launch(void* const* d_in, const int* in_sizes, int n_in,
                              void* d_out, int out_size)
{
    const float* q  = (const float*)d_in[0];
    const float* k  = (const float*)d_in[1];
    const float* v  = (const float*)d_in[2];
    const float* Wq = (const float*)d_in[3];
    const float* bq = (const float*)d_in[4];
    const float* Wk = (const float*)d_in[5];
    const float* bk = (const float*)d_in[6];
    const float* Wv = (const float*)d_in[7];
    const float* bv = (const float*)d_in[8];
    const float* Wo = (const float*)d_in[9];
    const float* bo = (const float*)d_in[10];

    float* out = (float*)d_out;
    float* probs = (out_size >= 138412032) ? out + 4194304 : nullptr;

    static int smem_set = 0;
    if (!smem_set) {
        cudaFuncSetAttribute(pav_kernel, cudaFuncAttributeMaxDynamicSharedMemorySize, PAV_SMEM_);
        smem_set = 1;
    }

    dim3 gemmGrid(8, 32, 1);
    gemm_wmma<<<gemmGrid, 256>>>(q, Wq, bq, nullptr, -1, 0);
    gemm_wmma<<<gemmGrid, 256>>>(k, Wk, bk, nullptr, -1, 1);
    gemm_wmma<<<gemmGrid, 256>>>(v, Wv, bv, nullptr, -1, 2);

    trans_qkv_kernel<<<1536, 256>>>();

    qk_wmma<<<dim3(16, 16, 32), 256>>>();

    // fused head-softmax + probs + AV
    pav_kernel<<<dim3(64, 2), 512, PAV_SMEM_>>>(probs);

    trans_attn_kernel<<<512, 256>>>();

    gemm_wmma<<<gemmGrid, 256>>>(nullptr, Wo, bo, out, 0, -1);
}

// round 16
// speedup vs baseline: 2.2657x; 1.8052x over previous
#include <cuda_runtime.h>
#include <cuda_fp16.h>
#include <mma.h>
#include <cstdint>
using namespace nvcuda;

#define B_   2
#define S_   2048
#define D_   1024
#define NH_  16
#define HD_  64
#define M_   4096
#define SS_  4194304
#define HEADSZ_ (2048*64)

// ---------------- scratch ----------------
__device__ __half g_rin[3u * 4194304u];          // half-rounded q/k/v inputs [p][m][k]
__device__ __half g_wh[4u * 1048576u];           // half-rounded weights [w][k][n]
__device__ float  g_lin3[3u * 4096u * 1024u];    // q/k/v linear outputs (fp32) [p][m][n]
__device__ __half g_qkv[3u * 32u * 2048u * 64u]; // head layout [p*32+bh][s][d] (half, Q pre-scaled /8)
__device__ float  g_scores[134217728u];          // [bh][l][n] raw scores (fp32)
__device__ float  g_attn[32u * 2048u * 64u];     // [bh][s][d] (fp32)
__device__ __half g_attnT[4096u * 1024u];        // interleaved [m][d*16+h] (half)

__device__ __forceinline__ int swz(int n) { return n ^ ((n >> 5) & 31); }

__device__ __forceinline__ void cpa16(void* dst, const void* src) {
    unsigned d = (unsigned)__cvta_generic_to_shared(dst);
    asm volatile("cp.async.ca.shared.global [%0], [%1], 16;\n" :: "r"(d), "l"(src));
}

// ---------------- round q/k/v inputs to half ----------------
__global__ void __launch_bounds__(256) round_in(const float* __restrict__ q,
                                                const float* __restrict__ k,
                                                const float* __restrict__ v)
{
    size_t i = (size_t)blockIdx.x * 256 + threadIdx.x;   // float4 index, < 3*1048576
    int p = (int)(i >> 20);
    size_t off = (i & 1048575u) * 4;
    const float* src = (p == 0) ? q : (p == 1) ? k : v;
    float4 x = *(const float4*)(src + off);
    __half2 h0 = __floats2half2_rn(x.x, x.y);
    __half2 h1 = __floats2half2_rn(x.z, x.w);
    *(__half2*)(g_rin + (size_t)p * 4194304u + off)     = h0;
    *(__half2*)(g_rin + (size_t)p * 4194304u + off + 2) = h1;
}

// ---------------- round weights to half (layout preserved [k][n]) ----------------
__global__ void __launch_bounds__(256) round_w(const float* __restrict__ W, int wsel)
{
    size_t i = (size_t)blockIdx.x * 256 + threadIdx.x;   // float4 index, < 262144
    size_t off = i * 4;
    float4 x = *(const float4*)(W + off);
    __half2 h0 = __floats2half2_rn(x.x, x.y);
    __half2 h1 = __floats2half2_rn(x.z, x.w);
    __half* dst = g_wh + (size_t)wsel * 1048576u + off;
    *(__half2*)(dst)     = h0;
    *(__half2*)(dst + 2) = h1;
}

// ============ fp16 GEMM: C[4096,1024] = A @ W + bias, fp32 accum ============
// 128x128 CTA tile, 8 warps (2x4), warp tile 64x32, m16n16k16, k-chunk 32, double-buffered.
__global__ void __launch_bounds__(256) gemm_h(const float* __restrict__ bias,
                                              float* __restrict__ Cout,
                                              int asel, int wsel, int csel)
{
    __shared__ __half As[2][128][40];
    __shared__ __half Bs[2][32][136];
    __shared__ float stage[8][16][20];

    const __half* A = (asel < 3) ? g_rin + (size_t)asel * 4194304u : g_attnT;
    const __half* W = g_wh + (size_t)wsel * 1048576u;
    float* C = (csel >= 0) ? g_lin3 + (size_t)csel * 4194304u : Cout;

    const int tid = threadIdx.x;
    const int warpId = tid >> 5, lane = tid & 31;
    const int wr = warpId >> 2, wc = warpId & 3;
    const int mBase = blockIdx.y * 128, nBase = blockIdx.x * 128;

    wmma::fragment<wmma::accumulator, 16, 16, 16, float> acc[4][2];
#pragma unroll
    for (int i = 0; i < 4; i++)
#pragma unroll
        for (int j = 0; j < 2; j++) wmma::fill_fragment(acc[i][j], 0.0f);

    auto loadChunk = [&](int c) {
        const int bb = c & 1;
        // A tile: 128 rows x 32 halves (4 segs of 8 halves)
#pragma unroll
        for (int i = 0; i < 2; i++) {
            int flat = i * 256 + tid;           // 0..511
            int row = flat >> 2, seg = flat & 3;
            cpa16(&As[bb][row][seg * 8], A + (size_t)(mBase + row) * 1024 + c * 32 + seg * 8);
        }
        // B tile: 32 rows x 128 halves (16 segs)
#pragma unroll
        for (int i = 0; i < 2; i++) {
            int flat = i * 256 + tid;           // 0..511
            int row = flat >> 4, seg = flat & 15;
            cpa16(&Bs[bb][row][seg * 8], W + (size_t)(c * 32 + row) * 1024 + nBase + seg * 8);
        }
        asm volatile("cp.async.commit_group;\n");
    };

    loadChunk(0);
    loadChunk(1);

    for (int c = 0; c < 32; c++) {
        if (c < 31) asm volatile("cp.async.wait_group 1;\n");
        else        asm volatile("cp.async.wait_group 0;\n");
        __syncthreads();

        const int bb = c & 1;
#pragma unroll
        for (int ks = 0; ks < 2; ks++) {
            wmma::fragment<wmma::matrix_a, 16, 16, 16, __half, wmma::row_major> af[4];
            wmma::fragment<wmma::matrix_b, 16, 16, 16, __half, wmma::row_major> bf[2];
#pragma unroll
            for (int i = 0; i < 4; i++)
                wmma::load_matrix_sync(af[i], &As[bb][wr * 64 + i * 16][ks * 16], 40);
#pragma unroll
            for (int j = 0; j < 2; j++)
                wmma::load_matrix_sync(bf[j], &Bs[bb][ks * 16][wc * 32 + j * 16], 136);
#pragma unroll
            for (int i = 0; i < 4; i++)
#pragma unroll
                for (int j = 0; j < 2; j++)
                    wmma::mma_sync(acc[i][j], af[i], bf[j], acc[i][j]);
        }
        __syncthreads();

        if (c + 2 < 32) loadChunk(c + 2);
    }

    // epilogue with bias
#pragma unroll
    for (int i = 0; i < 4; i++) {
#pragma unroll
        for (int j = 0; j < 2; j++) {
            wmma::store_matrix_sync(&stage[warpId][0][0], acc[i][j], 20, wmma::mem_row_major);
            __syncwarp();
            int r = lane >> 1, c0 = (lane & 1) * 8;
            int row = mBase + wr * 64 + i * 16 + r;
            int col = nBase + wc * 32 + j * 16 + c0;
            const float* sp = &stage[warpId][r][c0];
            float4 v0, v1;
            v0.x = sp[0] + bias[col + 0]; v0.y = sp[1] + bias[col + 1];
            v0.z = sp[2] + bias[col + 2]; v0.w = sp[3] + bias[col + 3];
            v1.x = sp[4] + bias[col + 4]; v1.y = sp[5] + bias[col + 5];
            v1.z = sp[6] + bias[col + 6]; v1.w = sp[7] + bias[col + 7];
            *(float4*)(C + (size_t)row * 1024 + col) = v0;
            *(float4*)(C + (size_t)row * 1024 + col + 4) = v1;
            __syncwarp();
        }
    }
}

// ---------------- interleaved (fp32) -> head layout (half, Q/8) ----------------
__global__ void __launch_bounds__(256) trans_qkv_kernel()
{
    __shared__ float buf[8][1024];
    const int w = threadIdx.x >> 5, lane = threadIdx.x & 31;
    const int r = blockIdx.x * 8 + w;
    const int p = r >> 12;
    const int bs = r & 4095;
    const int b = bs >> 11, s = bs & 2047;

    const float* src = g_lin3 + (size_t)r * 1024;
#pragma unroll
    for (int i = 0; i < 8; i++) {
        int n0 = i * 128 + lane * 4;
        float4 v = *(const float4*)(src + n0);
        buf[w][swz(n0 + 0)] = v.x;
        buf[w][swz(n0 + 1)] = v.y;
        buf[w][swz(n0 + 2)] = v.z;
        buf[w][swz(n0 + 3)] = v.w;
    }
    __syncwarp();
    const float sc = (p == 0) ? 0.125f : 1.0f;   // fold 1/sqrt(HD) into Q (exact pow2)
    __half* dstBase = g_qkv + ((size_t)p * 32 + (size_t)b * 16) * HEADSZ_ + (size_t)s * 64;
#pragma unroll
    for (int h = 0; h < 16; h++) {
        __half* dst = dstBase + (size_t)h * HEADSZ_;
#pragma unroll
        for (int half_ = 0; half_ < 2; half_++) {
            int d = half_ * 32 + lane;
            dst[d] = __float2half_rn(sc * buf[w][swz(d * 16 + h)]);
        }
    }
}

// ============ fp16 QK: scores[bh][l][n] = Q_h @ K_h^T (fp32 out) ============
// 128x128 tile, 8 warps (2x4), warp tile 64x32, K=64 loaded once.
__global__ void __launch_bounds__(256) qk_h()
{
    __shared__ __half Qs[128][72];
    __shared__ __half Ks[128][72];
    const int tid = threadIdx.x;
    const int warpId = tid >> 5;
    const int wr = warpId >> 2, wc = warpId & 3;
    const int bh = blockIdx.z;
    const int mBase = blockIdx.y * 128, nBase = blockIdx.x * 128;
    const __half* Q = g_qkv + (size_t)bh * HEADSZ_;
    const __half* K = g_qkv + (size_t)(32 + bh) * HEADSZ_;

    // load Q,K tiles: 128 rows x 64 halves = 8 segs/row
#pragma unroll
    for (int i = 0; i < 4; i++) {
        int flat = i * 256 + tid;               // 0..1023
        int row = flat >> 3, seg = flat & 7;
        cpa16(&Qs[row][seg * 8], Q + (size_t)(mBase + row) * 64 + seg * 8);
        cpa16(&Ks[row][seg * 8], K + (size_t)(nBase + row) * 64 + seg * 8);
    }
    asm volatile("cp.async.commit_group;\n");
    asm volatile("cp.async.wait_group 0;\n");
    __syncthreads();

    wmma::fragment<wmma::accumulator, 16, 16, 16, float> acc[4][2];
#pragma unroll
    for (int i = 0; i < 4; i++)
#pragma unroll
        for (int j = 0; j < 2; j++) wmma::fill_fragment(acc[i][j], 0.0f);

#pragma unroll
    for (int ks = 0; ks < 4; ks++) {
        wmma::fragment<wmma::matrix_a, 16, 16, 16, __half, wmma::row_major> af[4];
        wmma::fragment<wmma::matrix_b, 16, 16, 16, __half, wmma::col_major> bf[2];
#pragma unroll
        for (int i = 0; i < 4; i++)
            wmma::load_matrix_sync(af[i], &Qs[wr * 64 + i * 16][ks * 16], 72);
#pragma unroll
        for (int j = 0; j < 2; j++)
            wmma::load_matrix_sync(bf[j], &Ks[wc * 32 + j * 16][ks * 16], 72);
#pragma unroll
        for (int i = 0; i < 4; i++)
#pragma unroll
            for (int j = 0; j < 2; j++)
                wmma::mma_sync(acc[i][j], af[i], bf[j], acc[i][j]);
    }

    float* Cp = g_scores + (size_t)bh * SS_;
#pragma unroll
    for (int i = 0; i < 4; i++)
#pragma unroll
        for (int j = 0; j < 2; j++)
            wmma::store_matrix_sync(Cp + (size_t)(mBase + wr * 64 + i * 16) * 2048 +
                                    (nBase + wc * 32 + j * 16),
                                    acc[i][j], 2048, wmma::mem_row_major);
}

// ============ Fused head-softmax + probs write + AV (fp16 mma) ============
// Grid (64 l-tiles, 2 b), 512 threads (16 warps = 16 heads).
// smem: fp32 score double buffer [2][16][32][36] + half P region [16][32][40].
#define PLANE_ 1152
#define BUFW_  18432
#define PH_OFF_ (2 * BUFW_)                 // float offset of P half region
#define PAV_SMEM_ (2 * BUFW_ * 4 + 16 * 32 * 40 * 2)   // 147456 + 40960 = 188416

__global__ void __launch_bounds__(512) pav_kernel(float* __restrict__ probs_out)
{
    extern __shared__ float smf[];
    __half* Ph = (__half*)(smf + PH_OFF_);
    const int tid = threadIdx.x;
    const int h = tid >> 5;
    const int l0 = blockIdx.x * 32;
    const int b  = blockIdx.y;

    wmma::fragment<wmma::accumulator, 16, 16, 16, float> accO[2][4];
#pragma unroll
    for (int i = 0; i < 2; i++)
#pragma unroll
        for (int j = 0; j < 4; j++) wmma::fill_fragment(accO[i][j], 0.0f);

    auto load_chunk = [&](int chunk, int bbuf) {
#pragma unroll
        for (int i = 0; i < 8; i++) {
            int flat = i * 512 + tid;
            int hh  = flat >> 8;
            int row = (flat >> 3) & 31;
            int seg = flat & 7;
            const float* src = g_scores + (size_t)(b * 16 + hh) * SS_ +
                               (size_t)(l0 + row) * 2048 + chunk * 32 + seg * 4;
            cpa16(&smf[bbuf * BUFW_ + hh * PLANE_ + row * 36 + seg * 4], src);
        }
        asm volatile("cp.async.commit_group;\n");
    };

    load_chunk(0, 0);

    for (int c = 0; c < 64; c++) {
        const int bbuf = c & 1;
        if (c < 63) {
            load_chunk(c + 1, bbuf ^ 1);
            asm volatile("cp.async.wait_group 1;\n");
        } else {
            asm volatile("cp.async.wait_group 0;\n");
        }
        __syncthreads();

        float* buf = smf + bbuf * BUFW_;

        // softmax over heads: 2 (l,n) positions per thread; write probs + half P
#pragma unroll
        for (int p = 0; p < 2; p++) {
            int pos = p * 512 + tid;
            int l = pos >> 5, n = pos & 31;
            float* sp = buf + l * 36 + n;
            float v[16];
            float mx = -1e30f;
#pragma unroll
            for (int hh = 0; hh < 16; hh++) {
                v[hh] = sp[hh * PLANE_];
                mx = fmaxf(mx, v[hh]);
            }
            float s = 0.f;
#pragma unroll
            for (int hh = 0; hh < 16; hh++) {
                v[hh] = __expf(v[hh] - mx);
                s += v[hh];
            }
            float inv = 1.0f / s;
#pragma unroll
            for (int hh = 0; hh < 16; hh++) v[hh] *= inv;

            if (probs_out) {
                size_t gl = (size_t)(b * 2048 + l0 + l);
                size_t gn = (size_t)(c * 32 + n);
                float4* dst = (float4*)(probs_out + (gl * 2048 + gn) * 16);
                dst[0] = make_float4(v[0],  v[1],  v[2],  v[3]);
                dst[1] = make_float4(v[4],  v[5],  v[6],  v[7]);
                dst[2] = make_float4(v[8],  v[9],  v[10], v[11]);
                dst[3] = make_float4(v[12], v[13], v[14], v[15]);
            }
#pragma unroll
            for (int hh = 0; hh < 16; hh++)
                Ph[hh * 1280 + l * 40 + n] = __float2half_rn(v[hh]);
        }
        __syncthreads();

        // mma: warp h computes attn[l-tile][64] += P_h[32x32] @ V_h[32x64]
        {
            const __half* Pp = Ph + h * 1280;
            const __half* Vp = g_qkv + (size_t)(64 + b * 16 + h) * HEADSZ_ + (size_t)(c * 32) * 64;
#pragma unroll
            for (int ks = 0; ks < 2; ks++) {
                wmma::fragment<wmma::matrix_a, 16, 16, 16, __half, wmma::row_major> af[2];
                wmma::load_matrix_sync(af[0], Pp + ks * 16, 40);
                wmma::load_matrix_sync(af[1], Pp + 16 * 40 + ks * 16, 40);
#pragma unroll
                for (int j = 0; j < 4; j++) {
                    wmma::fragment<wmma::matrix_b, 16, 16, 16, __half, wmma::row_major> bfv;
                    wmma::load_matrix_sync(bfv, Vp + (size_t)ks * 16 * 64 + j * 16, 64);
                    wmma::mma_sync(accO[0][j], af[0], bfv, accO[0][j]);
                    wmma::mma_sync(accO[1][j], af[1], bfv, accO[1][j]);
                }
            }
        }
        __syncthreads();
    }

    float* C = g_attn + (size_t)(b * 16 + h) * HEADSZ_;
#pragma unroll
    for (int i = 0; i < 2; i++)
#pragma unroll
        for (int j = 0; j < 4; j++)
            wmma::store_matrix_sync(C + (size_t)(l0 + i * 16) * 64 + j * 16,
                                    accO[i][j], 64, wmma::mem_row_major);
}

// ---------------- head layout (fp32) -> interleaved (half) ----------------
__global__ void __launch_bounds__(256) trans_attn_kernel()
{
    __shared__ float buf[8][1024];
    const int w = threadIdx.x >> 5, lane = threadIdx.x & 31;
    const int r = blockIdx.x * 8 + w;
    const int b = r >> 11, s = r & 2047;

    const float* srcBase = g_attn + (size_t)b * 16u * HEADSZ_ + (size_t)s * 64;
#pragma unroll
    for (int h = 0; h < 16; h++) {
        const float* src = srcBase + (size_t)h * HEADSZ_;
#pragma unroll
        for (int half_ = 0; half_ < 2; half_++) {
            int d = half_ * 32 + lane;
            buf[w][swz(d * 16 + h)] = src[d];
        }
    }
    __syncwarp();
    __half* dst = g_attnT + (size_t)r * 1024;
#pragma unroll
    for (int i = 0; i < 8; i++) {
        int n0 = i * 128 + lane * 4;
        __half2 h0 = __floats2half2_rn(buf[w][swz(n0 + 0)], buf[w][swz(n0 + 1)]);
        __half2 h1 = __floats2half2_rn(buf[w][swz(n0 + 2)], buf[w][swz(n0 + 3)]);
        *(__half2*)(dst + n0)     = h0;
        *(__half2*)(dst + n0 + 2) = h1;
    }
}

// ---------------- launch ----------------
extern "C" void kernel_launch(void* const* d_in, const int* in_sizes, int n_in,
                              void* d_out, int out_size)
{
    const float* q  = (const float*)d_in[0];
    const float* k  = (const float*)d_in[1];
    const float* v  = (const float*)d_in[2];
    const float* Wq = (const float*)d_in[3];
    const float* bq = (const float*)d_in[4];
    const float* Wk = (const float*)d_in[5];
    const float* bk = (const float*)d_in[6];
    const float* Wv = (const float*)d_in[7];
    const float* bv = (const float*)d_in[8];
    const float* Wo = (const float*)d_in[9];
    const float* bo = (const float*)d_in[10];

    float* out = (float*)d_out;
    float* probs = (out_size >= 138412032) ? out + 4194304 : nullptr;

    static int smem_set = 0;
    if (!smem_set) {
        cudaFuncSetAttribute(pav_kernel, cudaFuncAttributeMaxDynamicSharedMemorySize, PAV_SMEM_);
        smem_set = 1;
    }

    // pre-round operands to half
    round_in<<<12288, 256>>>(q, k, v);
    round_w<<<1024, 256>>>(Wq, 0);
    round_w<<<1024, 256>>>(Wk, 1);
    round_w<<<1024, 256>>>(Wv, 2);
    round_w<<<1024, 256>>>(Wo, 3);

    dim3 gemmGrid(8, 32, 1);
    gemm_h<<<gemmGrid, 256>>>(bq, nullptr, 0, 0, 0);
    gemm_h<<<gemmGrid, 256>>>(bk, nullptr, 1, 1, 1);
    gemm_h<<<gemmGrid, 256>>>(bv, nullptr, 2, 2, 2);

    trans_qkv_kernel<<<1536, 256>>>();

    qk_h<<<dim3(16, 16, 32), 256>>>();

    // fused head-softmax + probs + AV
    pav_kernel<<<dim3(64, 2), 512, PAV_SMEM_>>>(probs);

    trans_attn_kernel<<<512, 256>>>();

    gemm_h<<<gemmGrid, 256>>>(bo, out, 3, 3, -1);
}

// round 17
// speedup vs baseline: 2.3595x; 1.0414x over previous
#include <cuda_runtime.h>
#include <cuda_fp16.h>
#include <mma.h>
#include <cstdint>
using namespace nvcuda;

#define B_   2
#define S_   2048
#define D_   1024
#define NH_  16
#define HD_  64
#define M_   4096
#define SS_  4194304
#define HEADSZ_ (2048*64)

// ---------------- scratch ----------------
__device__ __half g_rin[3u * 4194304u];          // half-rounded q/k/v inputs [p][m][k]
__device__ __half g_wh[4u * 1048576u];           // 0-2: col-permuted W (n'=h*64+d), 3: row-permuted Wo
__device__ float  g_bperm[3u * 1024u];           // col-permuted bq/bk/bv
__device__ __half g_qkv[3u * 32u * 2048u * 64u]; // head layout [p*32+bh][s][d] (half, Q pre-scaled /8)
__device__ float  g_scores[134217728u];          // [bh][l][n] raw scores (fp32)
__device__ __half g_attnT[4096u * 1024u];        // head-major [m][h*64+d] (half)

__device__ __forceinline__ void cpa16(void* dst, const void* src) {
    unsigned d = (unsigned)__cvta_generic_to_shared(dst);
    asm volatile("cp.async.ca.shared.global [%0], [%1], 16;\n" :: "r"(d), "l"(src));
}

// ---------------- one-shot: round inputs + permute/round weights + permute bias ----------------
__global__ void __launch_bounds__(256) round_all(const float* __restrict__ q,
                                                 const float* __restrict__ k,
                                                 const float* __restrict__ v,
                                                 const float* __restrict__ Wq,
                                                 const float* __restrict__ Wk,
                                                 const float* __restrict__ Wv,
                                                 const float* __restrict__ Wo,
                                                 const float* __restrict__ bq,
                                                 const float* __restrict__ bk,
                                                 const float* __restrict__ bv)
{
    const int bx = blockIdx.x;
    if (bx < 12288) {
        // q/k/v inputs -> half
        size_t i = (size_t)bx * 256 + threadIdx.x;       // float4 index
        int p = (int)(i >> 20);
        size_t off = (i & 1048575u) * 4;
        const float* src = (p == 0) ? q : (p == 1) ? k : v;
        float4 x = *(const float4*)(src + off);
        *(__half2*)(g_rin + (size_t)p * 4194304u + off)     = __floats2half2_rn(x.x, x.y);
        *(__half2*)(g_rin + (size_t)p * 4194304u + off + 2) = __floats2half2_rn(x.z, x.w);
    } else if (bx < 24576) {
        // Wq/Wk/Wv column permute: W'[k][h*64+d] = W[k][d*16+h]
        int r = bx - 12288;
        int w = r >> 12;                                  // 0..2
        size_t e = (size_t)(r & 4095) * 256 + threadIdx.x;  // elem 0..1048575
        int krow = (int)(e >> 10), np = (int)(e & 1023);
        int h = np >> 6, d = np & 63;
        const float* W = (w == 0) ? Wq : (w == 1) ? Wk : Wv;
        g_wh[(size_t)w * 1048576u + e] = __float2half_rn(W[(size_t)krow * 1024 + d * 16 + h]);
    } else if (bx < 25600) {
        // Wo row permute: Wo'[h*64+d][n] = Wo[d*16+h][n]
        int r = bx - 24576;                               // 0..1023
        size_t f4 = (size_t)r * 256 + threadIdx.x;        // float4 idx 0..262143
        int kp = (int)(f4 >> 8);                          // permuted row
        int seg = (int)(f4 & 255);
        int h = kp >> 6, d = kp & 63;
        float4 x = *(const float4*)(Wo + (size_t)(d * 16 + h) * 1024 + seg * 4);
        __half* dst = g_wh + 3u * 1048576u + (size_t)kp * 1024 + seg * 4;
        *(__half2*)(dst)     = __floats2half2_rn(x.x, x.y);
        *(__half2*)(dst + 2) = __floats2half2_rn(x.z, x.w);
    } else {
        // bias permute (fp32): b'[h*64+d] = b[d*16+h]
        int idx = (bx - 25600) * 256 + threadIdx.x;       // 0..3071
        int w = idx >> 10, np = idx & 1023;
        int h = np >> 6, d = np & 63;
        const float* bsrc = (w == 0) ? bq : (w == 1) ? bk : bv;
        g_bperm[idx] = bsrc[d * 16 + h];
    }
}

// ============ fp16 GEMM: 128x128 tile, m16n16k16, double-buffered ============
// csel 0..2: epilogue writes g_qkv (half, permuted bias, Q scaled /8)
// csel -1 : epilogue writes fp32 Cout + bias
__global__ void __launch_bounds__(256) gemm_h(const float* __restrict__ bias,
                                              float* __restrict__ Cout,
                                              int asel, int wsel, int csel)
{
    __shared__ __half As[2][128][40];
    __shared__ __half Bs[2][32][136];
    __shared__ float stage[8][16][20];

    const __half* A = (asel < 3) ? g_rin + (size_t)asel * 4194304u : g_attnT;
    const __half* W = g_wh + (size_t)wsel * 1048576u;

    const int tid = threadIdx.x;
    const int warpId = tid >> 5, lane = tid & 31;
    const int wr = warpId >> 2, wc = warpId & 3;
    const int mBase = blockIdx.y * 128, nBase = blockIdx.x * 128;

    wmma::fragment<wmma::accumulator, 16, 16, 16, float> acc[4][2];
#pragma unroll
    for (int i = 0; i < 4; i++)
#pragma unroll
        for (int j = 0; j < 2; j++) wmma::fill_fragment(acc[i][j], 0.0f);

    auto loadChunk = [&](int c) {
        const int bb = c & 1;
#pragma unroll
        for (int i = 0; i < 2; i++) {
            int flat = i * 256 + tid;
            int row = flat >> 2, seg = flat & 3;
            cpa16(&As[bb][row][seg * 8], A + (size_t)(mBase + row) * 1024 + c * 32 + seg * 8);
        }
#pragma unroll
        for (int i = 0; i < 2; i++) {
            int flat = i * 256 + tid;
            int row = flat >> 4, seg = flat & 15;
            cpa16(&Bs[bb][row][seg * 8], W + (size_t)(c * 32 + row) * 1024 + nBase + seg * 8);
        }
        asm volatile("cp.async.commit_group;\n");
    };

    loadChunk(0);
    loadChunk(1);

    for (int c = 0; c < 32; c++) {
        if (c < 31) asm volatile("cp.async.wait_group 1;\n");
        else        asm volatile("cp.async.wait_group 0;\n");
        __syncthreads();

        const int bb = c & 1;
#pragma unroll
        for (int ks = 0; ks < 2; ks++) {
            wmma::fragment<wmma::matrix_a, 16, 16, 16, __half, wmma::row_major> af[4];
            wmma::fragment<wmma::matrix_b, 16, 16, 16, __half, wmma::row_major> bf[2];
#pragma unroll
            for (int i = 0; i < 4; i++)
                wmma::load_matrix_sync(af[i], &As[bb][wr * 64 + i * 16][ks * 16], 40);
#pragma unroll
            for (int j = 0; j < 2; j++)
                wmma::load_matrix_sync(bf[j], &Bs[bb][ks * 16][wc * 32 + j * 16], 136);
#pragma unroll
            for (int i = 0; i < 4; i++)
#pragma unroll
                for (int j = 0; j < 2; j++)
                    wmma::mma_sync(acc[i][j], af[i], bf[j], acc[i][j]);
        }
        __syncthreads();

        if (c + 2 < 32) loadChunk(c + 2);
    }

    const float sc = (csel == 0) ? 0.125f : 1.0f;
    const float* bp = (csel >= 0) ? (g_bperm + csel * 1024) : bias;

#pragma unroll
    for (int i = 0; i < 4; i++) {
#pragma unroll
        for (int j = 0; j < 2; j++) {
            wmma::store_matrix_sync(&stage[warpId][0][0], acc[i][j], 20, wmma::mem_row_major);
            __syncwarp();
            int r = lane >> 1, c0 = (lane & 1) * 8;
            int row = mBase + wr * 64 + i * 16 + r;
            int col = nBase + wc * 32 + j * 16 + c0;
            const float* sp = &stage[warpId][r][c0];
            if (csel >= 0) {
                // half write into g_qkv head layout: col' = h*64 + d
                int h = col >> 6, d = col & 63;
                int b = row >> 11, s = row & 2047;
                __align__(16) __half2 hv[4];
#pragma unroll
                for (int t = 0; t < 4; t++)
                    hv[t] = __floats2half2_rn((sp[2 * t] + bp[col + 2 * t]) * sc,
                                              (sp[2 * t + 1] + bp[col + 2 * t + 1]) * sc);
                __half* dst = g_qkv + ((size_t)(csel * 32 + b * 16 + h) * 2048 + s) * 64 + d;
                *(uint4*)dst = *(const uint4*)hv;
            } else {
                float4 v0, v1;
                v0.x = sp[0] + bp[col + 0]; v0.y = sp[1] + bp[col + 1];
                v0.z = sp[2] + bp[col + 2]; v0.w = sp[3] + bp[col + 3];
                v1.x = sp[4] + bp[col + 4]; v1.y = sp[5] + bp[col + 5];
                v1.z = sp[6] + bp[col + 6]; v1.w = sp[7] + bp[col + 7];
                *(float4*)(Cout + (size_t)row * 1024 + col) = v0;
                *(float4*)(Cout + (size_t)row * 1024 + col + 4) = v1;
            }
            __syncwarp();
        }
    }
}

// ============ fp16 QK: scores[bh][l][n] = Q_h @ K_h^T (fp32 out) ============
__global__ void __launch_bounds__(256) qk_h()
{
    __shared__ __half Qs[128][72];
    __shared__ __half Ks[128][72];
    const int tid = threadIdx.x;
    const int warpId = tid >> 5;
    const int wr = warpId >> 2, wc = warpId & 3;
    const int bh = blockIdx.z;
    const int mBase = blockIdx.y * 128, nBase = blockIdx.x * 128;
    const __half* Q = g_qkv + (size_t)bh * HEADSZ_;
    const __half* K = g_qkv + (size_t)(32 + bh) * HEADSZ_;

#pragma unroll
    for (int i = 0; i < 4; i++) {
        int flat = i * 256 + tid;
        int row = flat >> 3, seg = flat & 7;
        cpa16(&Qs[row][seg * 8], Q + (size_t)(mBase + row) * 64 + seg * 8);
        cpa16(&Ks[row][seg * 8], K + (size_t)(nBase + row) * 64 + seg * 8);
    }
    asm volatile("cp.async.commit_group;\n");
    asm volatile("cp.async.wait_group 0;\n");
    __syncthreads();

    wmma::fragment<wmma::accumulator, 16, 16, 16, float> acc[4][2];
#pragma unroll
    for (int i = 0; i < 4; i++)
#pragma unroll
        for (int j = 0; j < 2; j++) wmma::fill_fragment(acc[i][j], 0.0f);

#pragma unroll
    for (int ks = 0; ks < 4; ks++) {
        wmma::fragment<wmma::matrix_a, 16, 16, 16, __half, wmma::row_major> af[4];
        wmma::fragment<wmma::matrix_b, 16, 16, 16, __half, wmma::col_major> bf[2];
#pragma unroll
        for (int i = 0; i < 4; i++)
            wmma::load_matrix_sync(af[i], &Qs[wr * 64 + i * 16][ks * 16], 72);
#pragma unroll
        for (int j = 0; j < 2; j++)
            wmma::load_matrix_sync(bf[j], &Ks[wc * 32 + j * 16][ks * 16], 72);
#pragma unroll
        for (int i = 0; i < 4; i++)
#pragma unroll
            for (int j = 0; j < 2; j++)
                wmma::mma_sync(acc[i][j], af[i], bf[j], acc[i][j]);
    }

    float* Cp = g_scores + (size_t)bh * SS_;
#pragma unroll
    for (int i = 0; i < 4; i++)
#pragma unroll
        for (int j = 0; j < 2; j++)
            wmma::store_matrix_sync(Cp + (size_t)(mBase + wr * 64 + i * 16) * 2048 +
                                    (nBase + wc * 32 + j * 16),
                                    acc[i][j], 2048, wmma::mem_row_major);
}

// ============ Fused head-softmax + probs write + AV + direct g_attnT epilogue ============
#define PLANE_ 1152
#define BUFW_  18432
#define PH_OFF_ (2 * BUFW_)
#define PAV_SMEM_ (2 * BUFW_ * 4 + 16 * 32 * 40 * 2)   // 188416

__global__ void __launch_bounds__(512) pav_kernel(float* __restrict__ probs_out)
{
    extern __shared__ float smf[];
    __half* Ph = (__half*)(smf + PH_OFF_);
    const int tid = threadIdx.x;
    const int h = tid >> 5;
    const int lane = tid & 31;
    const int l0 = blockIdx.x * 32;
    const int b  = blockIdx.y;

    wmma::fragment<wmma::accumulator, 16, 16, 16, float> accO[2][4];
#pragma unroll
    for (int i = 0; i < 2; i++)
#pragma unroll
        for (int j = 0; j < 4; j++) wmma::fill_fragment(accO[i][j], 0.0f);

    auto load_chunk = [&](int chunk, int bbuf) {
#pragma unroll
        for (int i = 0; i < 8; i++) {
            int flat = i * 512 + tid;
            int hh  = flat >> 8;
            int row = (flat >> 3) & 31;
            int seg = flat & 7;
            const float* src = g_scores + (size_t)(b * 16 + hh) * SS_ +
                               (size_t)(l0 + row) * 2048 + chunk * 32 + seg * 4;
            cpa16(&smf[bbuf * BUFW_ + hh * PLANE_ + row * 36 + seg * 4], src);
        }
        asm volatile("cp.async.commit_group;\n");
    };

    load_chunk(0, 0);

    for (int c = 0; c < 64; c++) {
        const int bbuf = c & 1;
        if (c < 63) {
            load_chunk(c + 1, bbuf ^ 1);
            asm volatile("cp.async.wait_group 1;\n");
        } else {
            asm volatile("cp.async.wait_group 0;\n");
        }
        __syncthreads();

        float* buf = smf + bbuf * BUFW_;

#pragma unroll
        for (int p = 0; p < 2; p++) {
            int pos = p * 512 + tid;
            int l = pos >> 5, n = pos & 31;
            float* sp = buf + l * 36 + n;
            float v[16];
            float mx = -1e30f;
#pragma unroll
            for (int hh = 0; hh < 16; hh++) {
                v[hh] = sp[hh * PLANE_];
                mx = fmaxf(mx, v[hh]);
            }
            float s = 0.f;
#pragma unroll
            for (int hh = 0; hh < 16; hh++) {
                v[hh] = __expf(v[hh] - mx);
                s += v[hh];
            }
            float inv = 1.0f / s;
#pragma unroll
            for (int hh = 0; hh < 16; hh++) v[hh] *= inv;

            if (probs_out) {
                size_t gl = (size_t)(b * 2048 + l0 + l);
                size_t gn = (size_t)(c * 32 + n);
                float4* dst = (float4*)(probs_out + (gl * 2048 + gn) * 16);
                dst[0] = make_float4(v[0],  v[1],  v[2],  v[3]);
                dst[1] = make_float4(v[4],  v[5],  v[6],  v[7]);
                dst[2] = make_float4(v[8],  v[9],  v[10], v[11]);
                dst[3] = make_float4(v[12], v[13], v[14], v[15]);
            }
#pragma unroll
            for (int hh = 0; hh < 16; hh++)
                Ph[hh * 1280 + l * 40 + n] = __float2half_rn(v[hh]);
        }
        __syncthreads();

        {
            const __half* Pp = Ph + h * 1280;
            const __half* Vp = g_qkv + (size_t)(64 + b * 16 + h) * HEADSZ_ + (size_t)(c * 32) * 64;
#pragma unroll
            for (int ks = 0; ks < 2; ks++) {
                wmma::fragment<wmma::matrix_a, 16, 16, 16, __half, wmma::row_major> af[2];
                wmma::load_matrix_sync(af[0], Pp + ks * 16, 40);
                wmma::load_matrix_sync(af[1], Pp + 16 * 40 + ks * 16, 40);
#pragma unroll
                for (int j = 0; j < 4; j++) {
                    wmma::fragment<wmma::matrix_b, 16, 16, 16, __half, wmma::row_major> bfv;
                    wmma::load_matrix_sync(bfv, Vp + (size_t)ks * 16 * 64 + j * 16, 64);
                    wmma::mma_sync(accO[0][j], af[0], bfv, accO[0][j]);
                    wmma::mma_sync(accO[1][j], af[1], bfv, accO[1][j]);
                }
            }
        }
        __syncthreads();
    }

    // ---- epilogue: stage fp32 in (now-free) score smem, write half head-major g_attnT ----
    __syncthreads();
    float* stg = smf + h * 2176;                 // 32x68 floats per warp
#pragma unroll
    for (int i = 0; i < 2; i++)
#pragma unroll
        for (int j = 0; j < 4; j++)
            wmma::store_matrix_sync(stg + (size_t)i * 16 * 68 + j * 16, accO[i][j], 68,
                                    wmma::mem_row_major);
    __syncwarp();
#pragma unroll
    for (int p = 0; p < 8; p++) {
        int r = p * 4 + (lane >> 3);
        int seg = lane & 7;
        const float* sp = stg + r * 68 + seg * 8;
        __align__(16) __half2 hv[4];
#pragma unroll
        for (int t = 0; t < 4; t++)
            hv[t] = __floats2half2_rn(sp[2 * t], sp[2 * t + 1]);
        __half* dst = g_attnT + (size_t)(b * 2048 + l0 + r) * 1024 + h * 64 + seg * 8;
        *(uint4*)dst = *(const uint4*)hv;
    }
}

// ---------------- launch ----------------
extern "C" void kernel_launch(void* const* d_in, const int* in_sizes, int n_in,
                              void* d_out, int out_size)
{
    const float* q  = (const float*)d_in[0];
    const float* k  = (const float*)d_in[1];
    const float* v  = (const float*)d_in[2];
    const float* Wq = (const float*)d_in[3];
    const float* bq = (const float*)d_in[4];
    const float* Wk = (const float*)d_in[5];
    const float* bk = (const float*)d_in[6];
    const float* Wv = (const float*)d_in[7];
    const float* bv = (const float*)d_in[8];
    const float* Wo = (const float*)d_in[9];
    const float* bo = (const float*)d_in[10];

    float* out = (float*)d_out;
    float* probs = (out_size >= 138412032) ? out + 4194304 : nullptr;

    static int smem_set = 0;
    if (!smem_set) {
        cudaFuncSetAttribute(pav_kernel, cudaFuncAttributeMaxDynamicSharedMemorySize, PAV_SMEM_);
        smem_set = 1;
    }

    // 1: round inputs + permute/round weights + permute bias
    round_all<<<25612, 256>>>(q, k, v, Wq, Wk, Wv, Wo, bq, bk, bv);

    dim3 gemmGrid(8, 32, 1);
    // 2-4: projections -> g_qkv directly (half, head layout, Q/8)
    gemm_h<<<gemmGrid, 256>>>(nullptr, nullptr, 0, 0, 0);
    gemm_h<<<gemmGrid, 256>>>(nullptr, nullptr, 1, 1, 1);
    gemm_h<<<gemmGrid, 256>>>(nullptr, nullptr, 2, 2, 2);

    // 5: scores
    qk_h<<<dim3(16, 16, 32), 256>>>();

    // 6: fused head-softmax + probs + AV -> g_attnT directly
    pav_kernel<<<dim3(64, 2), 512, PAV_SMEM_>>>(probs);

    // 7: output projection (row-permuted Wo, fp32 out + bo)
    gemm_h<<<gemmGrid, 256>>>(bo, out, 3, 3, -1);
}